// round 8
// baseline (speedup 1.0000x reference)
#include <cuda_runtime.h>

#define BC      128            // B*C = 8*16
#define B_DIM   8
#define C_DIM   16
#define HW      147456         // 384*384
#define HW4     36864          // HW/4 (float4 per class)
#define SPLIT   12             // blocks per class
#define BLK4    (HW4 / SPLIT)  // 3072 float4 per block per array
#define HALF4   (BLK4 / 2)     // 1536
#define NTHREADS 256
#define ITERS   (HALF4 / NTHREADS)   // 6
#define NBLOCKS (BC * SPLIT)         // 1536

#define ALPHA   0.05f
#define SMOOTH  1e-6f

// scratch: [NBLOCKS][5] partials: {sum_d2t, sum_d2, sum_t, max_t, max_p}
__device__ float g_part[NBLOCKS * 5];
__device__ int   g_count = 0;

__global__ __launch_bounds__(NTHREADS)
void fused_kernel(const float4* __restrict__ no,
                  const float4* __restrict__ tg,
                  const float4* __restrict__ mp,
                  float* __restrict__ out)
{
    const int cls  = blockIdx.x / SPLIT;
    const int part = blockIdx.x % SPLIT;
    const long base = (long)cls * HW4 + (long)part * BLK4;

    const int wid = threadIdx.x >> 5;
    const int lid = threadIdx.x & 31;
    const int NW  = NTHREADS / 32;

    float s_d2t = 0.f, s_d2 = 0.f, s_t = 0.f;
    float mxt = -1e30f;

    const float4* tl = tg + base + threadIdx.x;
    const float4* th = tg + base + HALF4 + threadIdx.x;
    const float4* nl = no + base + threadIdx.x;
    const float4* nh = no + base + HALF4 + threadIdx.x;

    // 4 independent load streams per iteration
    #pragma unroll 1
    for (int k = 0; k < ITERS; k++) {
        const int idx = k * NTHREADS;
        float4 t0 = tl[idx];
        float4 t1 = th[idx];
        float4 n0 = nl[idx];
        float4 n1 = nh[idx];

        float d;
        d = t0.x - n0.x; float a0 = d * d;
        d = t0.y - n0.y; float a1 = d * d;
        d = t0.z - n0.z; float a2 = d * d;
        d = t0.w - n0.w; float a3 = d * d;
        s_d2  += a0 + a1 + a2 + a3;
        s_d2t += a0 * t0.x + a1 * t0.y + a2 * t0.z + a3 * t0.w;
        s_t   += t0.x + t0.y + t0.z + t0.w;
        mxt = fmaxf(mxt, fmaxf(fmaxf(t0.x, t0.y), fmaxf(t0.z, t0.w)));

        d = t1.x - n1.x; float b0 = d * d;
        d = t1.y - n1.y; float b1 = d * d;
        d = t1.z - n1.z; float b2 = d * d;
        d = t1.w - n1.w; float b3 = d * d;
        s_d2  += b0 + b1 + b2 + b3;
        s_d2t += b0 * t1.x + b1 * t1.y + b2 * t1.z + b3 * t1.w;
        s_t   += t1.x + t1.y + t1.z + t1.w;
        mxt = fmaxf(mxt, fmaxf(fmaxf(t1.x, t1.y), fmaxf(t1.z, t1.w)));
    }

    #pragma unroll
    for (int off = 16; off > 0; off >>= 1) {
        s_d2t += __shfl_xor_sync(0xffffffff, s_d2t, off);
        s_d2  += __shfl_xor_sync(0xffffffff, s_d2,  off);
        s_t   += __shfl_xor_sync(0xffffffff, s_t,   off);
        mxt = fmaxf(mxt, __shfl_xor_sync(0xffffffff, mxt, off));
    }

    __shared__ float sh[NTHREADS / 32][4];
    __shared__ float sh_blkmax;
    if (lid == 0) {
        sh[wid][0] = s_d2t; sh[wid][1] = s_d2; sh[wid][2] = s_t; sh[wid][3] = mxt;
    }
    __syncthreads();

    if (wid == 0) {
        float v0 = (lid < NW) ? sh[lid][0] : 0.f;
        float v1 = (lid < NW) ? sh[lid][1] : 0.f;
        float v2 = (lid < NW) ? sh[lid][2] : 0.f;
        float v3 = (lid < NW) ? sh[lid][3] : -1e30f;
        #pragma unroll
        for (int off = 4; off > 0; off >>= 1) {
            v0 += __shfl_xor_sync(0xffffffff, v0, off);
            v1 += __shfl_xor_sync(0xffffffff, v1, off);
            v2 += __shfl_xor_sync(0xffffffff, v2, off);
            v3 = fmaxf(v3, __shfl_xor_sync(0xffffffff, v3, off));
        }
        if (lid == 0) {
            sh[0][0] = v0; sh[0][1] = v1; sh[0][2] = v2;
            sh_blkmax = v3;
        }
    }
    __syncthreads();

    // rare pass: mp only matters if this block's target region is all-zero
    // (if any t>0, the class is active and this block's mxp is never consulted)
    float mxp = -1e30f;
    if (sh_blkmax == 0.0f) {
        const float4* pp = mp + base + threadIdx.x;
        for (int k = 0; k < BLK4 / NTHREADS; k++) {
            float4 p = pp[k * NTHREADS];
            mxp = fmaxf(mxp, fmaxf(fmaxf(p.x, p.y), fmaxf(p.z, p.w)));
        }
        #pragma unroll
        for (int off = 16; off > 0; off >>= 1)
            mxp = fmaxf(mxp, __shfl_xor_sync(0xffffffff, mxp, off));
        __shared__ float shp[NTHREADS / 32];
        if (lid == 0) shp[wid] = mxp;
        __syncthreads();
        if (wid == 0) {
            float v = (lid < NW) ? shp[lid] : -1e30f;
            #pragma unroll
            for (int off = 4; off > 0; off >>= 1)
                v = fmaxf(v, __shfl_xor_sync(0xffffffff, v, off));
            mxp = v;
        }
    }

    __shared__ bool s_last;
    if (threadIdx.x == 0) {
        float* dst = &g_part[(long)blockIdx.x * 5];
        dst[0] = sh[0][0]; dst[1] = sh[0][1]; dst[2] = sh[0][2];
        dst[3] = sh_blkmax; dst[4] = mxp;
        __threadfence();
        int old = atomicAdd(&g_count, 1);
        s_last = (old == NBLOCKS - 1);
    }
    __syncthreads();

    if (!s_last) return;

    // ---- fused epilogue: last block reduces all partials ----
    __shared__ float losses[BC];
    __shared__ float imgl[B_DIM];

    if (threadIdx.x < BC) {
        const int c = threadIdx.x;
        float a_d2t = 0.f, a_d2 = 0.f, a_t = 0.f;
        float a_mt = -1e30f, a_mp = -1e30f;
        #pragma unroll
        for (int j = 0; j < SPLIT; j++) {
            const float* src = &g_part[(long)(c * SPLIT + j) * 5];
            a_d2t += __ldcg(src + 0);
            a_d2  += __ldcg(src + 1);
            a_t   += __ldcg(src + 2);
            a_mt = fmaxf(a_mt, __ldcg(src + 3));
            a_mp = fmaxf(a_mp, __ldcg(src + 4));
        }
        float m1 = a_d2t;
        float m2 = a_d2 - a_d2t;
        float d1 = a_t;
        float d2 = (float)HW - a_t;
        float loss = ALPHA * m1 / (d1 + SMOOTH) + (1.0f - ALPHA) * m2 / (d2 + SMOOTH);
        bool active = !((a_mt == 0.0f) && (a_mp == 0.0f));
        losses[c] = active ? loss : 0.0f;
    }
    __syncthreads();

    if (threadIdx.x < B_DIM) {
        float s = 0.f, cnt = 0.f;
        #pragma unroll
        for (int c = 0; c < C_DIM; c++) {
            float v = losses[threadIdx.x * C_DIM + c];
            s += v;
            if (v != 0.0f) cnt += 1.0f;
        }
        imgl[threadIdx.x] = s / cnt;
    }
    __syncthreads();

    if (threadIdx.x == 0) {
        float s = 0.f;
        #pragma unroll
        for (int b = 0; b < B_DIM; b++) s += imgl[b];
        out[0] = s / (float)B_DIM;
        g_count = 0;   // reset for next graph replay (deterministic)
    }
}

extern "C" void kernel_launch(void* const* d_in, const int* in_sizes, int n_in,
                              void* d_out, int out_size)
{
    const float4* no = (const float4*)d_in[0];   // net_out
    const float4* tg = (const float4*)d_in[1];   // target
    const float4* mp = (const float4*)d_in[2];   // max_positiones

    fused_kernel<<<NBLOCKS, NTHREADS>>>(no, tg, mp, (float*)d_out);
}

// round 9
// speedup vs baseline: 1.0611x; 1.0611x over previous
#include <cuda_runtime.h>

#define BC      128            // B*C = 8*16
#define B_DIM   8
#define C_DIM   16
#define HW      147456         // 384*384
#define HW4     36864          // HW/4 (float4 per class)
#define SPLIT   12             // blocks per class
#define BLK4    (HW4 / SPLIT)  // 3072 float4 per block per array
#define HALF4   (BLK4 / 2)     // 1536
#define NTHREADS 256
#define ITERS   (HALF4 / NTHREADS)   // 6
#define NBLOCKS (BC * SPLIT)         // 1536

#define ALPHA   0.05f
#define SMOOTH  1e-6f

// scratch: [NBLOCKS][5] partials: {sum_d2t, sum_d2, sum_t, max_t, max_p}
__device__ float g_part[NBLOCKS * 5];
__device__ int   g_count = 0;

__global__ __launch_bounds__(NTHREADS)
void fused_kernel(const float4* __restrict__ no,
                  const float4* __restrict__ tg,
                  const float4* __restrict__ mp,
                  float* __restrict__ out)
{
    const int cls  = blockIdx.x / SPLIT;
    const int part = blockIdx.x % SPLIT;
    const long base = (long)cls * HW4 + (long)part * BLK4;

    const int wid = threadIdx.x >> 5;
    const int lid = threadIdx.x & 31;
    const int NW  = NTHREADS / 32;

    float s_d2t = 0.f, s_d2 = 0.f, s_t = 0.f;
    float mxt = -1e30f;

    const float4* tl = tg + base + threadIdx.x;
    const float4* th = tg + base + HALF4 + threadIdx.x;
    const float4* nl = no + base + threadIdx.x;
    const float4* nh = no + base + HALF4 + threadIdx.x;

    // 4 independent load streams per iteration; let the compiler pick the
    // unroll/pipelining (forcing unroll 1 in R8 cost 12%; hand-batching in
    // R4 collapsed occupancy).
    for (int k = 0; k < ITERS; k++) {
        const int idx = k * NTHREADS;
        float4 t0 = tl[idx];
        float4 t1 = th[idx];
        float4 n0 = nl[idx];
        float4 n1 = nh[idx];

        float d;
        d = t0.x - n0.x; float a0 = d * d;
        d = t0.y - n0.y; float a1 = d * d;
        d = t0.z - n0.z; float a2 = d * d;
        d = t0.w - n0.w; float a3 = d * d;
        s_d2  += a0 + a1 + a2 + a3;
        s_d2t += a0 * t0.x + a1 * t0.y + a2 * t0.z + a3 * t0.w;
        s_t   += t0.x + t0.y + t0.z + t0.w;
        mxt = fmaxf(mxt, fmaxf(fmaxf(t0.x, t0.y), fmaxf(t0.z, t0.w)));

        d = t1.x - n1.x; float b0 = d * d;
        d = t1.y - n1.y; float b1 = d * d;
        d = t1.z - n1.z; float b2 = d * d;
        d = t1.w - n1.w; float b3 = d * d;
        s_d2  += b0 + b1 + b2 + b3;
        s_d2t += b0 * t1.x + b1 * t1.y + b2 * t1.z + b3 * t1.w;
        s_t   += t1.x + t1.y + t1.z + t1.w;
        mxt = fmaxf(mxt, fmaxf(fmaxf(t1.x, t1.y), fmaxf(t1.z, t1.w)));
    }

    #pragma unroll
    for (int off = 16; off > 0; off >>= 1) {
        s_d2t += __shfl_xor_sync(0xffffffff, s_d2t, off);
        s_d2  += __shfl_xor_sync(0xffffffff, s_d2,  off);
        s_t   += __shfl_xor_sync(0xffffffff, s_t,   off);
        mxt = fmaxf(mxt, __shfl_xor_sync(0xffffffff, mxt, off));
    }

    __shared__ float sh[NTHREADS / 32][4];
    __shared__ float sh_blkmax;
    if (lid == 0) {
        sh[wid][0] = s_d2t; sh[wid][1] = s_d2; sh[wid][2] = s_t; sh[wid][3] = mxt;
    }
    __syncthreads();

    if (wid == 0) {
        float v0 = (lid < NW) ? sh[lid][0] : 0.f;
        float v1 = (lid < NW) ? sh[lid][1] : 0.f;
        float v2 = (lid < NW) ? sh[lid][2] : 0.f;
        float v3 = (lid < NW) ? sh[lid][3] : -1e30f;
        #pragma unroll
        for (int off = 4; off > 0; off >>= 1) {
            v0 += __shfl_xor_sync(0xffffffff, v0, off);
            v1 += __shfl_xor_sync(0xffffffff, v1, off);
            v2 += __shfl_xor_sync(0xffffffff, v2, off);
            v3 = fmaxf(v3, __shfl_xor_sync(0xffffffff, v3, off));
        }
        if (lid == 0) {
            sh[0][0] = v0; sh[0][1] = v1; sh[0][2] = v2;
            sh_blkmax = v3;
        }
    }
    __syncthreads();

    // rare pass: mp only matters if this block's target region is all-zero
    // (if any t>0, the class is active and this block's mxp is never consulted)
    float mxp = -1e30f;
    if (sh_blkmax == 0.0f) {
        const float4* pp = mp + base + threadIdx.x;
        for (int k = 0; k < BLK4 / NTHREADS; k++) {
            float4 p = pp[k * NTHREADS];
            mxp = fmaxf(mxp, fmaxf(fmaxf(p.x, p.y), fmaxf(p.z, p.w)));
        }
        #pragma unroll
        for (int off = 16; off > 0; off >>= 1)
            mxp = fmaxf(mxp, __shfl_xor_sync(0xffffffff, mxp, off));
        __shared__ float shp[NTHREADS / 32];
        if (lid == 0) shp[wid] = mxp;
        __syncthreads();
        if (wid == 0) {
            float v = (lid < NW) ? shp[lid] : -1e30f;
            #pragma unroll
            for (int off = 4; off > 0; off >>= 1)
                v = fmaxf(v, __shfl_xor_sync(0xffffffff, v, off));
            mxp = v;
        }
    }

    __shared__ bool s_last;
    if (threadIdx.x == 0) {
        float* dst = &g_part[(long)blockIdx.x * 5];
        dst[0] = sh[0][0]; dst[1] = sh[0][1]; dst[2] = sh[0][2];
        dst[3] = sh_blkmax; dst[4] = mxp;
        __threadfence();
        int old = atomicAdd(&g_count, 1);
        s_last = (old == NBLOCKS - 1);
    }
    __syncthreads();

    if (!s_last) return;

    // ---- fused epilogue: last block reduces all partials ----
    __shared__ float losses[BC];
    __shared__ float imgl[B_DIM];

    if (threadIdx.x < BC) {
        const int c = threadIdx.x;
        float a_d2t = 0.f, a_d2 = 0.f, a_t = 0.f;
        float a_mt = -1e30f, a_mp = -1e30f;
        #pragma unroll
        for (int j = 0; j < SPLIT; j++) {
            const float* src = &g_part[(long)(c * SPLIT + j) * 5];
            a_d2t += __ldcg(src + 0);
            a_d2  += __ldcg(src + 1);
            a_t   += __ldcg(src + 2);
            a_mt = fmaxf(a_mt, __ldcg(src + 3));
            a_mp = fmaxf(a_mp, __ldcg(src + 4));
        }
        float m1 = a_d2t;
        float m2 = a_d2 - a_d2t;
        float d1 = a_t;
        float d2 = (float)HW - a_t;
        float loss = ALPHA * m1 / (d1 + SMOOTH) + (1.0f - ALPHA) * m2 / (d2 + SMOOTH);
        bool active = !((a_mt == 0.0f) && (a_mp == 0.0f));
        losses[c] = active ? loss : 0.0f;
    }
    __syncthreads();

    if (threadIdx.x < B_DIM) {
        float s = 0.f, cnt = 0.f;
        #pragma unroll
        for (int c = 0; c < C_DIM; c++) {
            float v = losses[threadIdx.x * C_DIM + c];
            s += v;
            if (v != 0.0f) cnt += 1.0f;
        }
        imgl[threadIdx.x] = s / cnt;
    }
    __syncthreads();

    if (threadIdx.x == 0) {
        float s = 0.f;
        #pragma unroll
        for (int b = 0; b < B_DIM; b++) s += imgl[b];
        out[0] = s / (float)B_DIM;
        g_count = 0;   // reset for next graph replay (deterministic)
    }
}

extern "C" void kernel_launch(void* const* d_in, const int* in_sizes, int n_in,
                              void* d_out, int out_size)
{
    const float4* no = (const float4*)d_in[0];   // net_out
    const float4* tg = (const float4*)d_in[1];   // target
    const float4* mp = (const float4*)d_in[2];   // max_positiones

    fused_kernel<<<NBLOCKS, NTHREADS>>>(no, tg, mp, (float*)d_out);
}